// round 1
// baseline (speedup 1.0000x reference)
#include <cuda_runtime.h>
#include <math.h>

// Problem constants
#define Bv   4
#define Tv   4096
#define Dv   1024
#define Hv   16
#define Wv   64
#define NWv  64
#define Mv   (Bv * Tv)      // 16384 token rows
#define K3v  (3 * Dv)       // 3072

// ---------------- scratch (device globals; no runtime allocation) ----------
__device__ float g_qkv[(size_t)Mv * K3v];     // [M, 3072]  q|k|v
__device__ float g_local[(size_t)Mv * Dv];    // [M, 1024]  windowed-attn output
__device__ float g_scores[Mv];                // row-sum of tanh(x W_cross^T)
__device__ float g_sum[Bv * NWv * Dv];        // window summaries  [256,1024]
__device__ float g_cs[Bv * NWv * Dv];         // cross-summary out [256,1024]

// ---------------------------------------------------------------------------
// Generic 128x128x8 SGEMM, C[m,n] = sum_k A[m,k] * Bw[n,k]  (both K-major)
// MODE 0: A = x, Bw = W_qkv, write g_qkv                       (N = 3072)
// MODE 1: A = x, Bw = W_cross; epilogue: atomicAdd row-sum of tanh(c + bias)
// MODE 2: A = g_local + 0.25*g_cs[row>>6], Bw = W_out, C = out + bias
// ---------------------------------------------------------------------------
template <int MODE>
__global__ void __launch_bounds__(256, 2)
gemm_k(const float* __restrict__ A, const float* __restrict__ Bw,
       float* __restrict__ C, const float* __restrict__ bias, int N)
{
    const int K = Dv;
    __shared__ __align__(16) float As[8][128];
    __shared__ __align__(16) float Bs[8][128];

    const int tid  = threadIdx.x;
    const int row0 = blockIdx.y * 128;
    const int col0 = blockIdx.x * 128;
    const int lr   = tid >> 1;          // 0..127
    const int lk   = (tid & 1) * 4;     // 0 or 4
    const int tx   = tid & 15;
    const int ty   = tid >> 4;

    float acc[8][8];
#pragma unroll
    for (int i = 0; i < 8; i++)
#pragma unroll
        for (int j = 0; j < 8; j++) acc[i][j] = 0.f;

    for (int kt = 0; kt < K; kt += 8) {
        float4 av;
        const int arow = row0 + lr;
        if (MODE == 2) {
            const float4 l4 = *(const float4*)(g_local + (size_t)arow * Dv + kt + lk);
            const float4 c4 = *(const float4*)(g_cs + (size_t)(arow >> 6) * Dv + kt + lk);
            av.x = l4.x + 0.25f * c4.x;
            av.y = l4.y + 0.25f * c4.y;
            av.z = l4.z + 0.25f * c4.z;
            av.w = l4.w + 0.25f * c4.w;
        } else {
            av = *(const float4*)(A + (size_t)arow * K + kt + lk);
        }
        const float4 bv = *(const float4*)(Bw + (size_t)(col0 + lr) * K + kt + lk);

        As[lk + 0][lr] = av.x; As[lk + 1][lr] = av.y;
        As[lk + 2][lr] = av.z; As[lk + 3][lr] = av.w;
        Bs[lk + 0][lr] = bv.x; Bs[lk + 1][lr] = bv.y;
        Bs[lk + 2][lr] = bv.z; Bs[lk + 3][lr] = bv.w;
        __syncthreads();

#pragma unroll
        for (int kk = 0; kk < 8; kk++) {
            float a[8], b[8];
            *(float4*)(a)     = *(const float4*)&As[kk][ty * 8];
            *(float4*)(a + 4) = *(const float4*)&As[kk][ty * 8 + 4];
            *(float4*)(b)     = *(const float4*)&Bs[kk][tx * 8];
            *(float4*)(b + 4) = *(const float4*)&Bs[kk][tx * 8 + 4];
#pragma unroll
            for (int i = 0; i < 8; i++)
#pragma unroll
                for (int j = 0; j < 8; j++) acc[i][j] += a[i] * b[j];
        }
        __syncthreads();
    }

    if (MODE == 0) {
#pragma unroll
        for (int i = 0; i < 8; i++) {
            const int row = row0 + ty * 8 + i;
            float* cp = g_qkv + (size_t)row * N + col0 + tx * 8;
            *(float4*)cp       = make_float4(acc[i][0], acc[i][1], acc[i][2], acc[i][3]);
            *(float4*)(cp + 4) = make_float4(acc[i][4], acc[i][5], acc[i][6], acc[i][7]);
        }
    } else if (MODE == 1) {
#pragma unroll
        for (int i = 0; i < 8; i++) {
            float s = 0.f;
#pragma unroll
            for (int j = 0; j < 8; j++)
                s += tanhf(acc[i][j] + bias[col0 + tx * 8 + j]);
            atomicAdd(&g_scores[row0 + ty * 8 + i], s);
        }
    } else {
#pragma unroll
        for (int i = 0; i < 8; i++) {
            const int row = row0 + ty * 8 + i;
            float* cp = C + (size_t)row * N + col0 + tx * 8;
            float4 v0, v1;
            v0.x = acc[i][0] + bias[col0 + tx * 8 + 0];
            v0.y = acc[i][1] + bias[col0 + tx * 8 + 1];
            v0.z = acc[i][2] + bias[col0 + tx * 8 + 2];
            v0.w = acc[i][3] + bias[col0 + tx * 8 + 3];
            v1.x = acc[i][4] + bias[col0 + tx * 8 + 4];
            v1.y = acc[i][5] + bias[col0 + tx * 8 + 5];
            v1.z = acc[i][6] + bias[col0 + tx * 8 + 6];
            v1.w = acc[i][7] + bias[col0 + tx * 8 + 7];
            *(float4*)cp       = v0;
            *(float4*)(cp + 4) = v1;
        }
    }
}

// ---------------------------------------------------------------------------
// Windowed attention: one CTA per (b, h, n). 64x64x64 per window.
// smem: shA = q then v (stride 64); shB = k^T (stride 65) then P (stride 64).
// ---------------------------------------------------------------------------
__global__ void __launch_bounds__(256)
attn_k()
{
    __shared__ __align__(16) float shA[64 * 64];
    __shared__ __align__(16) float shB[64 * 65];

    const int blk = blockIdx.x;
    const int n = blk & 63;
    const int h = (blk >> 6) & 15;
    const int b = blk >> 10;
    const int tid = threadIdx.x;

    const float* base = g_qkv + ((size_t)(b * Tv + n * 64)) * K3v + h * 64;
    const int lr = tid >> 4;          // 0..15
    const int lc = (tid & 15) * 4;    // 0..60

    // load q (row-major) and k (transposed, padded stride 65)
#pragma unroll
    for (int it = 0; it < 4; it++) {
        const int r = lr + it * 16;
        const float* rp = base + (size_t)r * K3v;
        const float4 q4 = *(const float4*)(rp + lc);
        const float4 k4 = *(const float4*)(rp + Dv + lc);
        *(float4*)&shA[r * 64 + lc] = q4;
        shB[(lc + 0) * 65 + r] = k4.x;
        shB[(lc + 1) * 65 + r] = k4.y;
        shB[(lc + 2) * 65 + r] = k4.z;
        shB[(lc + 3) * 65 + r] = k4.w;
    }
    __syncthreads();

    const int tx = tid & 15;
    const int ty = tid >> 4;

    // S = q k^T * scale (4x4 per thread: rows ty*4+i, cols tx*4+j)
    float acc[4][4];
#pragma unroll
    for (int i = 0; i < 4; i++)
#pragma unroll
        for (int j = 0; j < 4; j++) acc[i][j] = 0.f;

#pragma unroll 8
    for (int kk = 0; kk < 64; kk++) {
        float a[4], bb[4];
#pragma unroll
        for (int i = 0; i < 4; i++) a[i] = shA[(ty * 4 + i) * 64 + kk];
#pragma unroll
        for (int j = 0; j < 4; j++) bb[j] = shB[kk * 65 + tx * 4 + j];
#pragma unroll
        for (int i = 0; i < 4; i++)
#pragma unroll
            for (int j = 0; j < 4; j++) acc[i][j] += a[i] * bb[j];
    }
#pragma unroll
    for (int i = 0; i < 4; i++)
#pragma unroll
        for (int j = 0; j < 4; j++) acc[i][j] *= 0.125f;   // HD^-0.5

    // softmax per row across the 16 tx lanes (lane bits 0..3 = tx)
#pragma unroll
    for (int i = 0; i < 4; i++) {
        float m = acc[i][0];
#pragma unroll
        for (int j = 1; j < 4; j++) m = fmaxf(m, acc[i][j]);
#pragma unroll
        for (int off = 1; off < 16; off <<= 1)
            m = fmaxf(m, __shfl_xor_sync(0xffffffffu, m, off));
        float s = 0.f;
#pragma unroll
        for (int j = 0; j < 4; j++) { acc[i][j] = __expf(acc[i][j] - m); s += acc[i][j]; }
#pragma unroll
        for (int off = 1; off < 16; off <<= 1)
            s += __shfl_xor_sync(0xffffffffu, s, off);
        const float inv = 1.f / s;
#pragma unroll
        for (int j = 0; j < 4; j++) acc[i][j] *= inv;
    }
    __syncthreads();   // phase-1 smem reads complete

    // P -> shB (stride 64), v -> shA
#pragma unroll
    for (int i = 0; i < 4; i++)
        *(float4*)&shB[(ty * 4 + i) * 64 + tx * 4] =
            make_float4(acc[i][0], acc[i][1], acc[i][2], acc[i][3]);
#pragma unroll
    for (int it = 0; it < 4; it++) {
        const int r = lr + it * 16;
        const float4 v4 = *(const float4*)(base + (size_t)r * K3v + 2 * Dv + lc);
        *(float4*)&shA[r * 64 + lc] = v4;
    }
    __syncthreads();

    // O = P @ v
    float o[4][4];
#pragma unroll
    for (int i = 0; i < 4; i++)
#pragma unroll
        for (int j = 0; j < 4; j++) o[i][j] = 0.f;
#pragma unroll 8
    for (int kk = 0; kk < 64; kk++) {
        float a[4], bb[4];
#pragma unroll
        for (int i = 0; i < 4; i++) a[i] = shB[(ty * 4 + i) * 64 + kk];
#pragma unroll
        for (int j = 0; j < 4; j++) bb[j] = shA[kk * 64 + tx * 4 + j];
#pragma unroll
        for (int i = 0; i < 4; i++)
#pragma unroll
            for (int j = 0; j < 4; j++) o[i][j] += a[i] * bb[j];
    }

    float* op = g_local + ((size_t)(b * Tv + n * 64)) * Dv + h * 64;
#pragma unroll
    for (int i = 0; i < 4; i++)
        *(float4*)(op + (size_t)(ty * 4 + i) * Dv + tx * 4) =
            make_float4(o[i][0], o[i][1], o[i][2], o[i][3]);
}

// ---------------------------------------------------------------------------
__global__ void zero_scores_k()
{
    const int i = blockIdx.x * blockDim.x + threadIdx.x;
    if (i < Mv) g_scores[i] = 0.f;
}

// Window softmax of mean-tanh scores + weighted sum of x -> summaries.
// One CTA per (b, n); token base row = blockIdx.x * 64.
__global__ void __launch_bounds__(256)
summary_k(const float* __restrict__ x)
{
    __shared__ float wsh[64];
    const int blk = blockIdx.x;          // b*64 + n
    const int base = blk * 64;           // == b*T + n*64
    const int tid = threadIdx.x;

    if (tid < 64) wsh[tid] = g_scores[base + tid] * (1.0f / 1024.0f);
    __syncthreads();

    float mx = -1e30f;
    for (int w = 0; w < 64; w++) mx = fmaxf(mx, wsh[w]);
    float sum = 0.f;
    for (int w = 0; w < 64; w++) sum += __expf(wsh[w] - mx);
    __syncthreads();
    if (tid < 64) wsh[tid] = __expf(wsh[tid] - mx) / sum;
    __syncthreads();

    for (int d = tid; d < Dv; d += 256) {
        float acc = 0.f;
        const float* xp = x + (size_t)base * Dv + d;
#pragma unroll 8
        for (int w = 0; w < 64; w++) acc += wsh[w] * xp[(size_t)w * Dv];
        g_sum[(size_t)blk * Dv + d] = acc;
    }
}

// Cross-summary attention. One CTA per (b, n).
__global__ void __launch_bounds__(256)
cs_k(const int* __restrict__ jitter)
{
    __shared__ float lg[64];
    __shared__ float p[64];
    __shared__ int jit[64];
    const int blk = blockIdx.x;
    const int b = blk >> 6;
    const int tid = threadIdx.x;

    if (tid < 64) jit[tid] = jitter[tid];
    __syncthreads();

    const float* srow = g_sum + (size_t)blk * Dv;
    const int wid = tid >> 5, lane = tid & 31;
    for (int m8 = 0; m8 < 8; m8++) {
        const int m = wid * 8 + m8;
        const float* jrow = g_sum + (size_t)(b * 64 + jit[m]) * Dv;
        float a = 0.f;
        for (int d = lane; d < Dv; d += 32) a += srow[d] * jrow[d];
#pragma unroll
        for (int off = 16; off; off >>= 1) a += __shfl_xor_sync(0xffffffffu, a, off);
        if (lane == 0) lg[m] = a * (1.0f / 32.0f);   // D^-0.5
    }
    __syncthreads();

    float mx = -1e30f;
    for (int m = 0; m < 64; m++) mx = fmaxf(mx, lg[m]);
    float sum = 0.f;
    for (int m = 0; m < 64; m++) sum += __expf(lg[m] - mx);
    __syncthreads();
    if (tid < 64) p[tid] = __expf(lg[tid] - mx) / sum;
    __syncthreads();

    for (int d = tid; d < Dv; d += 256) {
        float acc = 0.f;
#pragma unroll 8
        for (int m = 0; m < 64; m++)
            acc += p[m] * g_sum[(size_t)(b * 64 + jit[m]) * Dv + d];
        g_cs[(size_t)blk * Dv + d] = acc;
    }
}

// ---------------------------------------------------------------------------
extern "C" void kernel_launch(void* const* d_in, const int* in_sizes, int n_in,
                              void* d_out, int out_size)
{
    const float* x       = (const float*)d_in[0];
    const float* W_qkv   = (const float*)d_in[1];
    const float* W_out   = (const float*)d_in[2];
    const float* b_out   = (const float*)d_in[3];
    const float* W_cross = (const float*)d_in[4];
    const float* b_cross = (const float*)d_in[5];
    const int*   jitter  = (const int*)d_in[6];
    float* out = (float*)d_out;

    zero_scores_k<<<16, 1024>>>();
    gemm_k<0><<<dim3(24, 128), 256>>>(x, W_qkv, nullptr, nullptr, K3v);       // qkv
    gemm_k<1><<<dim3(8, 128), 256>>>(x, W_cross, nullptr, b_cross, Dv);       // tanh-mean scores
    attn_k<<<Bv * Hv * NWv, 256>>>();                                         // windowed attention
    summary_k<<<Bv * NWv, 256>>>(x);                                          // window summaries
    cs_k<<<Bv * NWv, 256>>>(jitter);                                          // cross-summary attn
    gemm_k<2><<<dim3(8, 128), 256>>>(nullptr, W_out, out, b_out, Dv);         // final projection
}

// round 3
// speedup vs baseline: 5.2783x; 5.2783x over previous
#include <cuda_runtime.h>
#include <cuda_fp16.h>
#include <math.h>
#include <stdint.h>

// Problem constants
#define Bv   4
#define Tv   4096
#define Dv   1024
#define NWv  64
#define Mv   16384          // B*T token rows
#define K3v  3072

// ---------------- scratch (device globals; no runtime allocation) ----------
__device__ __half g_xh[(size_t)Mv * Dv];        // x in fp16
__device__ __half g_wqkvh[(size_t)K3v * Dv];    // W_qkv fp16
__device__ __half g_wcrossh[(size_t)Dv * Dv];   // W_cross fp16
__device__ __half g_wouth[(size_t)Dv * Dv];     // W_out fp16
__device__ __half g_qkvh[(size_t)Mv * K3v];     // qkv fp16
__device__ __half g_localh[(size_t)Mv * Dv];    // windowed-attn out fp16
__device__ __half g_a2h[(size_t)Mv * Dv];       // local + 0.25*cs, fp16
__device__ float  g_scores[Mv];
__device__ float  g_sum[Bv * NWv * Dv];
__device__ float  g_cs[Bv * NWv * Dv];

// ---------------------------------------------------------------------------
__device__ __forceinline__ uint32_t smem_u32(const void* p) {
    uint32_t a;
    asm("{ .reg .u64 t; cvta.to.shared.u64 t, %1; cvt.u32.u64 %0, t; }"
        : "=r"(a) : "l"(p));
    return a;
}
#define CP16(dst, src) \
    asm volatile("cp.async.cg.shared.global [%0], [%1], 16;" :: "r"(dst), "l"(src))
#define CPCOMMIT() asm volatile("cp.async.commit_group;" ::: "memory")
#define CPWAIT0()  asm volatile("cp.async.wait_group 0;" ::: "memory")

__device__ __forceinline__ void mma16816(float* d, const uint32_t* a, const uint32_t* b) {
    asm volatile(
        "mma.sync.aligned.m16n8k16.row.col.f32.f16.f16.f32 "
        "{%0,%1,%2,%3}, {%4,%5,%6,%7}, {%8,%9}, {%0,%1,%2,%3};"
        : "+f"(d[0]), "+f"(d[1]), "+f"(d[2]), "+f"(d[3])
        : "r"(a[0]), "r"(a[1]), "r"(a[2]), "r"(a[3]), "r"(b[0]), "r"(b[1]));
}

// ---------------------------------------------------------------------------
// fp32 -> fp16 conversion (vectorized)
// ---------------------------------------------------------------------------
__global__ void cvt_half_k(const float* __restrict__ s, __half* __restrict__ d, int n4)
{
    const int i = blockIdx.x * blockDim.x + threadIdx.x;
    if (i < n4) {
        const float4 v = ((const float4*)s)[i];
        ((__half2*)d)[i * 2]     = __floats2half2_rn(v.x, v.y);
        ((__half2*)d)[i * 2 + 1] = __floats2half2_rn(v.z, v.w);
    }
}

// ---------------------------------------------------------------------------
// fp16 tensor-core GEMM: C[m,n] = sum_k A[m,k]*Bw[n,k], K=1024.
// CTA 128x128, BK=64 halfs, cp.async double-buffer, 8 warps (2m x 4n), warp 64x32.
// SMEM: per buffer A[128][144B] + B[128][144B] (72-half stride: conflict-free frags).
// MODE 0: -> g_qkvh (half).  MODE 1: atomicAdd rowsum tanh(c+bias).
// MODE 2: -> Cf (f32) + bias.
// ---------------------------------------------------------------------------
#define TILEB 18432                     // 128 * 144
#define BUFB  (2 * TILEB)               // A + B per stage
#define SMEM_GEMM (2 * BUFB)            // 73728

template <int MODE>
__global__ void __launch_bounds__(256, 1)
hgemm(const __half* __restrict__ Ah, const __half* __restrict__ Bh,
      float* __restrict__ Cf, __half* __restrict__ Ch,
      const float* __restrict__ bias, int N)
{
    extern __shared__ __align__(16) char sm[];
    const int tid = threadIdx.x;
    const int w = tid >> 5, l = tid & 31;
    const int row0 = blockIdx.y * 128;
    const int col0 = blockIdx.x * 128;
    const int wm = (w >> 2) * 64;       // warp m-offset (0/64)
    const int wn = (w & 3) * 32;        // warp n-offset

    float acc[4][4][4];
#pragma unroll
    for (int a = 0; a < 4; a++)
#pragma unroll
        for (int b = 0; b < 4; b++)
#pragma unroll
            for (int c = 0; c < 4; c++) acc[a][b][c] = 0.f;

    const uint32_t sb = smem_u32(sm);

    // cp.async one BK=64 stage: A and B tiles, 4 x 16B per thread each.
    auto issue = [&](int t, int buf) {
        const __half* Asrc = Ah + (size_t)row0 * Dv + t * 64;
        const __half* Bsrc = Bh + (size_t)col0 * Dv + t * 64;
        const uint32_t dA = sb + buf * BUFB;
        const uint32_t dB = dA + TILEB;
#pragma unroll
        for (int it = 0; it < 4; it++) {
            const int idx = it * 256 + tid;
            const int m = idx >> 3, kq = idx & 7;        // row, 16B-chunk
            CP16(dA + m * 144 + kq * 16, Asrc + (size_t)m * Dv + kq * 8);
            CP16(dB + m * 144 + kq * 16, Bsrc + (size_t)m * Dv + kq * 8);
        }
        CPCOMMIT();
    };

    issue(0, 0);

    const int rA = (l >> 2) * 144;      // fragment row byte offset
    const int cA = (l & 3) * 4;         // fragment k byte offset (2 halfs)

    for (int t = 0; t < 16; t++) {
        CPWAIT0();
        __syncthreads();
        if (t + 1 < 16) issue(t + 1, (t + 1) & 1);

        const char* smA = sm + (t & 1) * BUFB + wm * 144;
        const char* smB = sm + (t & 1) * BUFB + TILEB + wn * 144;
#pragma unroll
        for (int kt = 0; kt < 4; kt++) {
            const int ko = kt * 32 + cA;
            uint32_t a[4][4], b[4][2];
#pragma unroll
            for (int mt = 0; mt < 4; mt++) {
                const char* p = smA + mt * 2304 + rA + ko;
                a[mt][0] = *(const uint32_t*)(p);
                a[mt][1] = *(const uint32_t*)(p + 1152);
                a[mt][2] = *(const uint32_t*)(p + 16);
                a[mt][3] = *(const uint32_t*)(p + 1168);
            }
#pragma unroll
            for (int nt = 0; nt < 4; nt++) {
                const char* p = smB + nt * 1152 + rA + ko;
                b[nt][0] = *(const uint32_t*)(p);
                b[nt][1] = *(const uint32_t*)(p + 16);
            }
#pragma unroll
            for (int mt = 0; mt < 4; mt++)
#pragma unroll
                for (int nt = 0; nt < 4; nt++)
                    mma16816(acc[mt][nt], a[mt], b[nt]);
        }
    }

    // ---- epilogue
    const int rbase = row0 + wm + (l >> 2);
    const int cbase = col0 + wn + (l & 3) * 2;

    if (MODE == 1) {
#pragma unroll
        for (int mt = 0; mt < 4; mt++) {
            float s0 = 0.f, s1 = 0.f;
#pragma unroll
            for (int nt = 0; nt < 4; nt++) {
                const int c = cbase + nt * 8;
                const float b0 = bias[c], b1 = bias[c + 1];
                s0 += tanhf(acc[mt][nt][0] + b0) + tanhf(acc[mt][nt][1] + b1);
                s1 += tanhf(acc[mt][nt][2] + b0) + tanhf(acc[mt][nt][3] + b1);
            }
            s0 += __shfl_xor_sync(0xffffffffu, s0, 1);
            s0 += __shfl_xor_sync(0xffffffffu, s0, 2);
            s1 += __shfl_xor_sync(0xffffffffu, s1, 1);
            s1 += __shfl_xor_sync(0xffffffffu, s1, 2);
            if ((l & 3) == 0) {
                atomicAdd(&g_scores[rbase + mt * 16], s0);
                atomicAdd(&g_scores[rbase + mt * 16 + 8], s1);
            }
        }
    } else if (MODE == 0) {
#pragma unroll
        for (int mt = 0; mt < 4; mt++) {
            const int row = rbase + mt * 16;
#pragma unroll
            for (int nt = 0; nt < 4; nt++) {
                const int col = cbase + nt * 8;
                *(__half2*)(Ch + (size_t)row * N + col) =
                    __floats2half2_rn(acc[mt][nt][0], acc[mt][nt][1]);
                *(__half2*)(Ch + (size_t)(row + 8) * N + col) =
                    __floats2half2_rn(acc[mt][nt][2], acc[mt][nt][3]);
            }
        }
    } else {
#pragma unroll
        for (int mt = 0; mt < 4; mt++) {
            const int row = rbase + mt * 16;
#pragma unroll
            for (int nt = 0; nt < 4; nt++) {
                const int col = cbase + nt * 8;
                const float b0 = bias[col], b1 = bias[col + 1];
                *(float2*)(Cf + (size_t)row * N + col) =
                    make_float2(acc[mt][nt][0] + b0, acc[mt][nt][1] + b1);
                *(float2*)(Cf + (size_t)(row + 8) * N + col) =
                    make_float2(acc[mt][nt][2] + b0, acc[mt][nt][3] + b1);
            }
        }
    }
}

// ---------------------------------------------------------------------------
// Windowed attention: one CTA per (b, h, n). 64x64x64, fp16 in/out, f32 math.
// ---------------------------------------------------------------------------
__global__ void __launch_bounds__(256)
attn_k()
{
    __shared__ __align__(16) float shA[64 * 64];
    __shared__ __align__(16) float shB[64 * 65];

    const int blk = blockIdx.x;
    const int n = blk & 63;
    const int h = (blk >> 6) & 15;
    const int b = blk >> 10;
    const int tid = threadIdx.x;

    const __half* base = g_qkvh + ((size_t)(b * Tv + n * 64)) * K3v + h * 64;
    const int lr = tid >> 4;
    const int lc = (tid & 15) * 4;

#pragma unroll
    for (int it = 0; it < 4; it++) {
        const int r = lr + it * 16;
        const __half* rp = base + (size_t)r * K3v;
        const float2 q0 = __half22float2(*(const __half2*)(rp + lc));
        const float2 q1 = __half22float2(*(const __half2*)(rp + lc + 2));
        const float2 k0 = __half22float2(*(const __half2*)(rp + Dv + lc));
        const float2 k1 = __half22float2(*(const __half2*)(rp + Dv + lc + 2));
        *(float4*)&shA[r * 64 + lc] = make_float4(q0.x, q0.y, q1.x, q1.y);
        shB[(lc + 0) * 65 + r] = k0.x;
        shB[(lc + 1) * 65 + r] = k0.y;
        shB[(lc + 2) * 65 + r] = k1.x;
        shB[(lc + 3) * 65 + r] = k1.y;
    }
    __syncthreads();

    const int tx = tid & 15;
    const int ty = tid >> 4;

    float acc[4][4];
#pragma unroll
    for (int i = 0; i < 4; i++)
#pragma unroll
        for (int j = 0; j < 4; j++) acc[i][j] = 0.f;

#pragma unroll 8
    for (int kk = 0; kk < 64; kk++) {
        float a[4], bb[4];
#pragma unroll
        for (int i = 0; i < 4; i++) a[i] = shA[(ty * 4 + i) * 64 + kk];
#pragma unroll
        for (int j = 0; j < 4; j++) bb[j] = shB[kk * 65 + tx * 4 + j];
#pragma unroll
        for (int i = 0; i < 4; i++)
#pragma unroll
            for (int j = 0; j < 4; j++) acc[i][j] += a[i] * bb[j];
    }
#pragma unroll
    for (int i = 0; i < 4; i++)
#pragma unroll
        for (int j = 0; j < 4; j++) acc[i][j] *= 0.125f;

#pragma unroll
    for (int i = 0; i < 4; i++) {
        float m = acc[i][0];
#pragma unroll
        for (int j = 1; j < 4; j++) m = fmaxf(m, acc[i][j]);
#pragma unroll
        for (int off = 1; off < 16; off <<= 1)
            m = fmaxf(m, __shfl_xor_sync(0xffffffffu, m, off));
        float s = 0.f;
#pragma unroll
        for (int j = 0; j < 4; j++) { acc[i][j] = __expf(acc[i][j] - m); s += acc[i][j]; }
#pragma unroll
        for (int off = 1; off < 16; off <<= 1)
            s += __shfl_xor_sync(0xffffffffu, s, off);
        const float inv = 1.f / s;
#pragma unroll
        for (int j = 0; j < 4; j++) acc[i][j] *= inv;
    }
    __syncthreads();

#pragma unroll
    for (int i = 0; i < 4; i++)
        *(float4*)&shB[(ty * 4 + i) * 64 + tx * 4] =
            make_float4(acc[i][0], acc[i][1], acc[i][2], acc[i][3]);
#pragma unroll
    for (int it = 0; it < 4; it++) {
        const int r = lr + it * 16;
        const __half* rp = base + (size_t)r * K3v + 2 * Dv;
        const float2 v0 = __half22float2(*(const __half2*)(rp + lc));
        const float2 v1 = __half22float2(*(const __half2*)(rp + lc + 2));
        *(float4*)&shA[r * 64 + lc] = make_float4(v0.x, v0.y, v1.x, v1.y);
    }
    __syncthreads();

    float o[4][4];
#pragma unroll
    for (int i = 0; i < 4; i++)
#pragma unroll
        for (int j = 0; j < 4; j++) o[i][j] = 0.f;
#pragma unroll 8
    for (int kk = 0; kk < 64; kk++) {
        float a[4], bb[4];
#pragma unroll
        for (int i = 0; i < 4; i++) a[i] = shB[(ty * 4 + i) * 64 + kk];
#pragma unroll
        for (int j = 0; j < 4; j++) bb[j] = shA[kk * 64 + tx * 4 + j];
#pragma unroll
        for (int i = 0; i < 4; i++)
#pragma unroll
            for (int j = 0; j < 4; j++) o[i][j] += a[i] * bb[j];
    }

    __half* op = g_localh + ((size_t)(b * Tv + n * 64)) * Dv + h * 64;
#pragma unroll
    for (int i = 0; i < 4; i++) {
        __half* wp = op + (size_t)(ty * 4 + i) * Dv + tx * 4;
        *(__half2*)(wp)     = __floats2half2_rn(o[i][0], o[i][1]);
        *(__half2*)(wp + 2) = __floats2half2_rn(o[i][2], o[i][3]);
    }
}

// ---------------------------------------------------------------------------
__global__ void zero_scores_k()
{
    const int i = blockIdx.x * blockDim.x + threadIdx.x;
    if (i < Mv) g_scores[i] = 0.f;
}

__global__ void __launch_bounds__(256)
summary_k(const float* __restrict__ x)
{
    __shared__ float wsh[64];
    const int blk = blockIdx.x;
    const int base = blk * 64;
    const int tid = threadIdx.x;

    if (tid < 64) wsh[tid] = g_scores[base + tid] * (1.0f / 1024.0f);
    __syncthreads();

    float mx = -1e30f;
    for (int w = 0; w < 64; w++) mx = fmaxf(mx, wsh[w]);
    float sum = 0.f;
    for (int w = 0; w < 64; w++) sum += __expf(wsh[w] - mx);
    __syncthreads();
    if (tid < 64) wsh[tid] = __expf(wsh[tid] - mx) / sum;
    __syncthreads();

    for (int d = tid; d < Dv; d += 256) {
        float acc = 0.f;
        const float* xp = x + (size_t)base * Dv + d;
#pragma unroll 8
        for (int w = 0; w < 64; w++) acc += wsh[w] * xp[(size_t)w * Dv];
        g_sum[(size_t)blk * Dv + d] = acc;
    }
}

__global__ void __launch_bounds__(256)
cs_k(const int* __restrict__ jitter)
{
    __shared__ float lg[64];
    __shared__ float p[64];
    __shared__ int jit[64];
    const int blk = blockIdx.x;
    const int b = blk >> 6;
    const int tid = threadIdx.x;

    if (tid < 64) jit[tid] = jitter[tid];
    __syncthreads();

    const float* srow = g_sum + (size_t)blk * Dv;
    const int wid = tid >> 5, lane = tid & 31;
    for (int m8 = 0; m8 < 8; m8++) {
        const int m = wid * 8 + m8;
        const float* jrow = g_sum + (size_t)(b * 64 + jit[m]) * Dv;
        float a = 0.f;
        for (int d = lane; d < Dv; d += 32) a += srow[d] * jrow[d];
#pragma unroll
        for (int off = 16; off; off >>= 1) a += __shfl_xor_sync(0xffffffffu, a, off);
        if (lane == 0) lg[m] = a * (1.0f / 32.0f);
    }
    __syncthreads();

    float mx = -1e30f;
    for (int m = 0; m < 64; m++) mx = fmaxf(mx, lg[m]);
    float sum = 0.f;
    for (int m = 0; m < 64; m++) sum += __expf(lg[m] - mx);
    __syncthreads();
    if (tid < 64) p[tid] = __expf(lg[tid] - mx) / sum;
    __syncthreads();

    for (int d = tid; d < Dv; d += 256) {
        float acc = 0.f;
#pragma unroll 8
        for (int m = 0; m < 64; m++)
            acc += p[m] * g_sum[(size_t)(b * 64 + jit[m]) * Dv + d];
        g_cs[(size_t)blk * Dv + d] = acc;
    }
}

// a2 = half(local + 0.25*cs[window])  (4 halfs per thread)
__global__ void fuse_k()
{
    const size_t i = (size_t)blockIdx.x * blockDim.x + threadIdx.x;
    const size_t e = i * 4;
    if (e < (size_t)Mv * Dv) {
        const int m = (int)(e >> 10), d = (int)(e & 1023);
        const __half2 l0 = *(const __half2*)(g_localh + e);
        const __half2 l1 = *(const __half2*)(g_localh + e + 2);
        const float4 c = *(const float4*)(g_cs + (size_t)(m >> 6) * Dv + d);
        const float2 f0 = __half22float2(l0), f1 = __half22float2(l1);
        *(__half2*)(g_a2h + e) =
            __floats2half2_rn(f0.x + 0.25f * c.x, f0.y + 0.25f * c.y);
        *(__half2*)(g_a2h + e + 2) =
            __floats2half2_rn(f1.x + 0.25f * c.z, f1.y + 0.25f * c.w);
    }
}

// ---------------------------------------------------------------------------
extern "C" void kernel_launch(void* const* d_in, const int* in_sizes, int n_in,
                              void* d_out, int out_size)
{
    const float* x       = (const float*)d_in[0];
    const float* W_qkv   = (const float*)d_in[1];
    const float* W_out   = (const float*)d_in[2];
    const float* b_out   = (const float*)d_in[3];
    const float* W_cross = (const float*)d_in[4];
    const float* b_cross = (const float*)d_in[5];
    const int*   jitter  = (const int*)d_in[6];
    float* out = (float*)d_out;

    static int attr_done = 0;
    if (!attr_done) {
        cudaFuncSetAttribute(hgemm<0>, cudaFuncAttributeMaxDynamicSharedMemorySize, SMEM_GEMM);
        cudaFuncSetAttribute(hgemm<1>, cudaFuncAttributeMaxDynamicSharedMemorySize, SMEM_GEMM);
        cudaFuncSetAttribute(hgemm<2>, cudaFuncAttributeMaxDynamicSharedMemorySize, SMEM_GEMM);
        attr_done = 1;
    }

    __half *xh, *wqkvh, *wcrossh, *wouth;
    cudaGetSymbolAddress((void**)&xh, g_xh);
    cudaGetSymbolAddress((void**)&wqkvh, g_wqkvh);
    cudaGetSymbolAddress((void**)&wcrossh, g_wcrossh);
    cudaGetSymbolAddress((void**)&wouth, g_wouth);
    __half *qkvh, *a2h;
    cudaGetSymbolAddress((void**)&qkvh, g_qkvh);
    cudaGetSymbolAddress((void**)&a2h, g_a2h);

    // fp32 -> fp16 conversions
    cvt_half_k<<<(Mv * Dv / 4 + 255) / 256, 256>>>(x, xh, Mv * Dv / 4);
    cvt_half_k<<<(K3v * Dv / 4 + 255) / 256, 256>>>(W_qkv, wqkvh, K3v * Dv / 4);
    cvt_half_k<<<(Dv * Dv / 4 + 255) / 256, 256>>>(W_cross, wcrossh, Dv * Dv / 4);
    cvt_half_k<<<(Dv * Dv / 4 + 255) / 256, 256>>>(W_out, wouth, Dv * Dv / 4);
    zero_scores_k<<<16, 1024>>>();

    hgemm<0><<<dim3(24, 128), 256, SMEM_GEMM>>>(xh, wqkvh, nullptr, qkvh, nullptr, K3v);
    hgemm<1><<<dim3(8, 128), 256, SMEM_GEMM>>>(xh, wcrossh, nullptr, nullptr, b_cross, Dv);
    attn_k<<<Bv * 16 * NWv, 256>>>();
    summary_k<<<Bv * NWv, 256>>>(x);
    cs_k<<<Bv * NWv, 256>>>(jitter);
    fuse_k<<<Mv * Dv / 4 / 256, 256>>>();
    hgemm<2><<<dim3(8, 128), 256, SMEM_GEMM>>>(a2h, wouth, out, nullptr, b_out, Dv);
}

// round 5
// speedup vs baseline: 5.8028x; 1.0994x over previous
#include <cuda_runtime.h>
#include <cuda_fp16.h>
#include <math.h>
#include <stdint.h>

// Problem constants
#define Bv   4
#define Tv   4096
#define Dv   1024
#define NWv  64
#define Mv   16384          // B*T token rows
#define K3v  3072

// ---------------- scratch (device globals; no runtime allocation) ----------
__device__ __half g_xh[(size_t)Mv * Dv];
__device__ __half g_wqkvh[(size_t)K3v * Dv];
__device__ __half g_wcrossh[(size_t)Dv * Dv];
__device__ __half g_wouth[(size_t)Dv * Dv];
__device__ __half g_qkvh[(size_t)Mv * K3v];
__device__ __half g_localh[(size_t)Mv * Dv];
__device__ __half g_a2h[(size_t)Mv * Dv];
__device__ float  g_scores[Mv];
__device__ float  g_sum[Bv * NWv * Dv];
__device__ float  g_cs[Bv * NWv * Dv];

// ---------------------------------------------------------------------------
__device__ __forceinline__ uint32_t smem_u32(const void* p) {
    uint32_t a;
    asm("{ .reg .u64 t; cvta.to.shared.u64 t, %1; cvt.u32.u64 %0, t; }"
        : "=r"(a) : "l"(p));
    return a;
}
#define CP16(dst, src) \
    asm volatile("cp.async.cg.shared.global [%0], [%1], 16;" :: "r"(dst), "l"(src))
#define CPCOMMIT() asm volatile("cp.async.commit_group;" ::: "memory")
#define CPWAIT0()  asm volatile("cp.async.wait_group 0;" ::: "memory")
#define CPWAIT1()  asm volatile("cp.async.wait_group 1;" ::: "memory")

__device__ __forceinline__ void mma16816(float* d, const uint32_t* a, const uint32_t* b) {
    asm volatile(
        "mma.sync.aligned.m16n8k16.row.col.f32.f16.f16.f32 "
        "{%0,%1,%2,%3}, {%4,%5,%6,%7}, {%8,%9}, {%0,%1,%2,%3};"
        : "+f"(d[0]), "+f"(d[1]), "+f"(d[2]), "+f"(d[3])
        : "r"(a[0]), "r"(a[1]), "r"(a[2]), "r"(a[3]), "r"(b[0]), "r"(b[1]));
}
// pack two f32 -> f16x2 register (single SASS cvt)
__device__ __forceinline__ uint32_t packh2(float x, float y) {
    uint32_t r;
    asm("cvt.rn.f16x2.f32 %0, %1, %2;" : "=r"(r) : "f"(y), "f"(x));
    return r;
}

// ---------------------------------------------------------------------------
__global__ void cvt_half_k(const float* __restrict__ s, __half* __restrict__ d, int n4)
{
    const int i = blockIdx.x * blockDim.x + threadIdx.x;
    if (i < n4) {
        const float4 v = ((const float4*)s)[i];
        ((__half2*)d)[i * 2]     = __floats2half2_rn(v.x, v.y);
        ((__half2*)d)[i * 2 + 1] = __floats2half2_rn(v.z, v.w);
    }
}

// ---------------------------------------------------------------------------
// fp16 tensor-core GEMM, CTA 128x128, BK=64, 3-stage cp.async pipeline.
// MODE 0: -> Ch (half).  MODE 1: atomicAdd rowsum tanh(c+bias).  MODE 2: -> Cf+bias.
// ---------------------------------------------------------------------------
#define TILEB 18432                     // 128 * 144
#define BUFB  (2 * TILEB)               // A + B per stage
#define SMEM_GEMM (3 * BUFB)            // 110592

template <int MODE>
__global__ void __launch_bounds__(256, 1)
hgemm(const __half* __restrict__ Ah, const __half* __restrict__ Bh,
      float* __restrict__ Cf, __half* __restrict__ Ch,
      const float* __restrict__ bias, int N)
{
    extern __shared__ __align__(16) char sm[];
    const int tid = threadIdx.x;
    const int w = tid >> 5, l = tid & 31;
    const int row0 = blockIdx.y * 128;
    const int col0 = blockIdx.x * 128;
    const int wm = (w >> 2) * 64;
    const int wn = (w & 3) * 32;

    float acc[4][4][4];
#pragma unroll
    for (int a = 0; a < 4; a++)
#pragma unroll
        for (int b = 0; b < 4; b++)
#pragma unroll
            for (int c = 0; c < 4; c++) acc[a][b][c] = 0.f;

    const uint32_t sb = smem_u32(sm);

    auto issue = [&](int t, int buf) {
        const __half* Asrc = Ah + (size_t)row0 * Dv + t * 64;
        const __half* Bsrc = Bh + (size_t)col0 * Dv + t * 64;
        const uint32_t dA = sb + buf * BUFB;
        const uint32_t dB = dA + TILEB;
#pragma unroll
        for (int it = 0; it < 4; it++) {
            const int idx = it * 256 + tid;
            const int m = idx >> 3, kq = idx & 7;
            CP16(dA + m * 144 + kq * 16, Asrc + (size_t)m * Dv + kq * 8);
            CP16(dB + m * 144 + kq * 16, Bsrc + (size_t)m * Dv + kq * 8);
        }
        CPCOMMIT();
    };

    issue(0, 0);
    issue(1, 1);

    const int rA = (l >> 2) * 144;
    const int cA = (l & 3) * 4;
    int buf = 0;

    for (int t = 0; t < 16; t++) {
        if (t < 15) CPWAIT1(); else CPWAIT0();
        __syncthreads();
        if (t + 2 < 16) {
            int nb = buf + 2; if (nb >= 3) nb -= 3;
            issue(t + 2, nb);
        }

        const char* smA = sm + buf * BUFB + wm * 144;
        const char* smB = sm + buf * BUFB + TILEB + wn * 144;
#pragma unroll
        for (int kt = 0; kt < 4; kt++) {
            const int ko = kt * 32 + cA;
            uint32_t a[4][4], b[4][2];
#pragma unroll
            for (int mt = 0; mt < 4; mt++) {
                const char* p = smA + mt * 2304 + rA + ko;
                a[mt][0] = *(const uint32_t*)(p);
                a[mt][1] = *(const uint32_t*)(p + 1152);
                a[mt][2] = *(const uint32_t*)(p + 16);
                a[mt][3] = *(const uint32_t*)(p + 1168);
            }
#pragma unroll
            for (int nt = 0; nt < 4; nt++) {
                const char* p = smB + nt * 1152 + rA + ko;
                b[nt][0] = *(const uint32_t*)(p);
                b[nt][1] = *(const uint32_t*)(p + 16);
            }
#pragma unroll
            for (int mt = 0; mt < 4; mt++)
#pragma unroll
                for (int nt = 0; nt < 4; nt++)
                    mma16816(acc[mt][nt], a[mt], b[nt]);
        }
        if (++buf == 3) buf = 0;
    }

    const int rbase = row0 + wm + (l >> 2);
    const int cbase = col0 + wn + (l & 3) * 2;

    if (MODE == 1) {
#pragma unroll
        for (int mt = 0; mt < 4; mt++) {
            float s0 = 0.f, s1 = 0.f;
#pragma unroll
            for (int nt = 0; nt < 4; nt++) {
                const int c = cbase + nt * 8;
                const float b0 = bias[c], b1 = bias[c + 1];
                s0 += tanhf(acc[mt][nt][0] + b0) + tanhf(acc[mt][nt][1] + b1);
                s1 += tanhf(acc[mt][nt][2] + b0) + tanhf(acc[mt][nt][3] + b1);
            }
            s0 += __shfl_xor_sync(0xffffffffu, s0, 1);
            s0 += __shfl_xor_sync(0xffffffffu, s0, 2);
            s1 += __shfl_xor_sync(0xffffffffu, s1, 1);
            s1 += __shfl_xor_sync(0xffffffffu, s1, 2);
            if ((l & 3) == 0) {
                atomicAdd(&g_scores[rbase + mt * 16], s0);
                atomicAdd(&g_scores[rbase + mt * 16 + 8], s1);
            }
        }
    } else if (MODE == 0) {
#pragma unroll
        for (int mt = 0; mt < 4; mt++) {
            const int row = rbase + mt * 16;
#pragma unroll
            for (int nt = 0; nt < 4; nt++) {
                const int col = cbase + nt * 8;
                *(__half2*)(Ch + (size_t)row * N + col) =
                    __floats2half2_rn(acc[mt][nt][0], acc[mt][nt][1]);
                *(__half2*)(Ch + (size_t)(row + 8) * N + col) =
                    __floats2half2_rn(acc[mt][nt][2], acc[mt][nt][3]);
            }
        }
    } else {
#pragma unroll
        for (int mt = 0; mt < 4; mt++) {
            const int row = rbase + mt * 16;
#pragma unroll
            for (int nt = 0; nt < 4; nt++) {
                const int col = cbase + nt * 8;
                const float b0 = bias[col], b1 = bias[col + 1];
                *(float2*)(Cf + (size_t)row * N + col) =
                    make_float2(acc[mt][nt][0] + b0, acc[mt][nt][1] + b1);
                *(float2*)(Cf + (size_t)(row + 8) * N + col) =
                    make_float2(acc[mt][nt][2] + b0, acc[mt][nt][3] + b1);
            }
        }
    }
}

// ---------------------------------------------------------------------------
// Tensor-core windowed attention: one CTA (128 thr, 4 warps) per (b, h, n).
// Warp w owns query rows w*16..w*16+15. S and O via mma.sync, softmax f32.
// ---------------------------------------------------------------------------
__global__ void __launch_bounds__(128)
attn_k()
{
    __shared__ __align__(16) __half sQ[64 * 72];
    __shared__ __align__(16) __half sK[64 * 72];
    __shared__ __align__(16) __half sVt[64 * 72];   // V transposed: [hd][token]

    const int blk = blockIdx.x;
    const int n = blk & 63;
    const int h = (blk >> 6) & 15;
    const int b = blk >> 10;
    const int tid = threadIdx.x;
    const int w = tid >> 5, l = tid & 31;

    const __half* base = g_qkvh + ((size_t)(b * Tv + n * 64)) * K3v + h * 64;

#pragma unroll
    for (int j = 0; j < 16; j++) {
        const int idx = j * 128 + tid;        // 0..2047 half2 slots
        const int r = idx >> 5, c2 = idx & 31;
        const __half* rp = base + (size_t)r * K3v;
        const __half2 qv = *(const __half2*)(rp + c2 * 2);
        const __half2 kv = *(const __half2*)(rp + Dv + c2 * 2);
        const __half2 vv = *(const __half2*)(rp + 2 * Dv + c2 * 2);
        *(__half2*)&sQ[r * 72 + c2 * 2] = qv;
        *(__half2*)&sK[r * 72 + c2 * 2] = kv;
        sVt[(c2 * 2) * 72 + r]     = __low2half(vv);
        sVt[(c2 * 2 + 1) * 72 + r] = __high2half(vv);
    }
    __syncthreads();

    const int gr = l >> 2;             // fragment row
    const int gc = (l & 3) * 2;        // fragment col pair

    // ---- S = Q K^T (scale applied after)
    float sacc[8][4];
#pragma unroll
    for (int nt = 0; nt < 8; nt++)
#pragma unroll
        for (int c = 0; c < 4; c++) sacc[nt][c] = 0.f;

#pragma unroll
    for (int kt = 0; kt < 4; kt++) {
        uint32_t a[4];
        const __half* qp = sQ + (w * 16 + gr) * 72 + kt * 16 + gc;
        a[0] = *(const uint32_t*)(qp);
        a[1] = *(const uint32_t*)(qp + 8 * 72);
        a[2] = *(const uint32_t*)(qp + 8);
        a[3] = *(const uint32_t*)(qp + 8 * 72 + 8);
#pragma unroll
        for (int nt = 0; nt < 8; nt++) {
            uint32_t bb[2];
            const __half* kp = sK + (nt * 8 + gr) * 72 + kt * 16 + gc;
            bb[0] = *(const uint32_t*)(kp);
            bb[1] = *(const uint32_t*)(kp + 8);
            mma16816(sacc[nt], a, bb);
        }
    }

    // ---- softmax (rows w*16+gr and +8); scale = 0.125
    float m0 = -1e30f, m1 = -1e30f;
#pragma unroll
    for (int nt = 0; nt < 8; nt++) {
#pragma unroll
        for (int c = 0; c < 4; c++) sacc[nt][c] *= 0.125f;
        m0 = fmaxf(m0, fmaxf(sacc[nt][0], sacc[nt][1]));
        m1 = fmaxf(m1, fmaxf(sacc[nt][2], sacc[nt][3]));
    }
    m0 = fmaxf(m0, __shfl_xor_sync(0xffffffffu, m0, 1));
    m0 = fmaxf(m0, __shfl_xor_sync(0xffffffffu, m0, 2));
    m1 = fmaxf(m1, __shfl_xor_sync(0xffffffffu, m1, 1));
    m1 = fmaxf(m1, __shfl_xor_sync(0xffffffffu, m1, 2));

    float s0 = 0.f, s1 = 0.f;
#pragma unroll
    for (int nt = 0; nt < 8; nt++) {
        sacc[nt][0] = __expf(sacc[nt][0] - m0);
        sacc[nt][1] = __expf(sacc[nt][1] - m0);
        sacc[nt][2] = __expf(sacc[nt][2] - m1);
        sacc[nt][3] = __expf(sacc[nt][3] - m1);
        s0 += sacc[nt][0] + sacc[nt][1];
        s1 += sacc[nt][2] + sacc[nt][3];
    }
    s0 += __shfl_xor_sync(0xffffffffu, s0, 1);
    s0 += __shfl_xor_sync(0xffffffffu, s0, 2);
    s1 += __shfl_xor_sync(0xffffffffu, s1, 1);
    s1 += __shfl_xor_sync(0xffffffffu, s1, 2);
    const float i0 = 1.f / s0, i1 = 1.f / s1;
#pragma unroll
    for (int nt = 0; nt < 8; nt++) {
        sacc[nt][0] *= i0; sacc[nt][1] *= i0;
        sacc[nt][2] *= i1; sacc[nt][3] *= i1;
    }

    // ---- O = P V   (P fragments straight from sacc; V via sVt)
    float oacc[8][4];
#pragma unroll
    for (int nt = 0; nt < 8; nt++)
#pragma unroll
        for (int c = 0; c < 4; c++) oacc[nt][c] = 0.f;

#pragma unroll
    for (int kt = 0; kt < 4; kt++) {
        uint32_t a[4];
        a[0] = packh2(sacc[2 * kt][0],     sacc[2 * kt][1]);
        a[1] = packh2(sacc[2 * kt][2],     sacc[2 * kt][3]);
        a[2] = packh2(sacc[2 * kt + 1][0], sacc[2 * kt + 1][1]);
        a[3] = packh2(sacc[2 * kt + 1][2], sacc[2 * kt + 1][3]);
#pragma unroll
        for (int nt = 0; nt < 8; nt++) {
            uint32_t bb[2];
            const __half* vp = sVt + (nt * 8 + gr) * 72 + kt * 16 + gc;
            bb[0] = *(const uint32_t*)(vp);
            bb[1] = *(const uint32_t*)(vp + 8);
            mma16816(oacc[nt], a, bb);
        }
    }

    __half* op = g_localh + ((size_t)(b * Tv + n * 64)) * Dv + h * 64;
    const int orow = w * 16 + gr;
#pragma unroll
    for (int nt = 0; nt < 8; nt++) {
        const int col = nt * 8 + gc;
        *(__half2*)(op + (size_t)orow * Dv + col) =
            __floats2half2_rn(oacc[nt][0], oacc[nt][1]);
        *(__half2*)(op + (size_t)(orow + 8) * Dv + col) =
            __floats2half2_rn(oacc[nt][2], oacc[nt][3]);
    }
}

// ---------------------------------------------------------------------------
__global__ void zero_scores_k()
{
    const int i = blockIdx.x * blockDim.x + threadIdx.x;
    if (i < Mv) g_scores[i] = 0.f;
}

__global__ void __launch_bounds__(256)
summary_k(const float* __restrict__ x)
{
    __shared__ float wsh[64];
    const int blk = blockIdx.x;
    const int base = blk * 64;
    const int tid = threadIdx.x;

    if (tid < 64) wsh[tid] = g_scores[base + tid] * (1.0f / 1024.0f);
    __syncthreads();

    float mx = -1e30f;
    for (int w = 0; w < 64; w++) mx = fmaxf(mx, wsh[w]);
    float sum = 0.f;
    for (int w = 0; w < 64; w++) sum += __expf(wsh[w] - mx);
    __syncthreads();
    if (tid < 64) wsh[tid] = __expf(wsh[tid] - mx) / sum;
    __syncthreads();

    for (int d = tid; d < Dv; d += 256) {
        float acc = 0.f;
        const float* xp = x + (size_t)base * Dv + d;
#pragma unroll 8
        for (int w = 0; w < 64; w++) acc += wsh[w] * xp[(size_t)w * Dv];
        g_sum[(size_t)blk * Dv + d] = acc;
    }
}

__global__ void __launch_bounds__(256)
cs_k(const int* __restrict__ jitter)
{
    __shared__ float lg[64];
    __shared__ float p[64];
    __shared__ int jit[64];
    const int blk = blockIdx.x;
    const int b = blk >> 6;
    const int tid = threadIdx.x;

    if (tid < 64) jit[tid] = jitter[tid];
    __syncthreads();

    const float* srow = g_sum + (size_t)blk * Dv;
    const int wid = tid >> 5, lane = tid & 31;
    for (int m8 = 0; m8 < 8; m8++) {
        const int m = wid * 8 + m8;
        const float* jrow = g_sum + (size_t)(b * 64 + jit[m]) * Dv;
        float a = 0.f;
        for (int d = lane; d < Dv; d += 32) a += srow[d] * jrow[d];
#pragma unroll
        for (int off = 16; off; off >>= 1) a += __shfl_xor_sync(0xffffffffu, a, off);
        if (lane == 0) lg[m] = a * (1.0f / 32.0f);
    }
    __syncthreads();

    float mx = -1e30f;
    for (int m = 0; m < 64; m++) mx = fmaxf(mx, lg[m]);
    float sum = 0.f;
    for (int m = 0; m < 64; m++) sum += __expf(lg[m] - mx);
    __syncthreads();
    if (tid < 64) p[tid] = __expf(lg[tid] - mx) / sum;
    __syncthreads();

    for (int d = tid; d < Dv; d += 256) {
        float acc = 0.f;
#pragma unroll 8
        for (int m = 0; m < 64; m++)
            acc += p[m] * g_sum[(size_t)(b * 64 + jit[m]) * Dv + d];
        g_cs[(size_t)blk * Dv + d] = acc;
    }
}

__global__ void fuse_k()
{
    const size_t i = (size_t)blockIdx.x * blockDim.x + threadIdx.x;
    const size_t e = i * 4;
    if (e < (size_t)Mv * Dv) {
        const int m = (int)(e >> 10), d = (int)(e & 1023);
        const __half2 l0 = *(const __half2*)(g_localh + e);
        const __half2 l1 = *(const __half2*)(g_localh + e + 2);
        const float4 c = *(const float4*)(g_cs + (size_t)(m >> 6) * Dv + d);
        const float2 f0 = __half22float2(l0), f1 = __half22float2(l1);
        *(__half2*)(g_a2h + e) =
            __floats2half2_rn(f0.x + 0.25f * c.x, f0.y + 0.25f * c.y);
        *(__half2*)(g_a2h + e + 2) =
            __floats2half2_rn(f1.x + 0.25f * c.z, f1.y + 0.25f * c.w);
    }
}

// ---------------------------------------------------------------------------
extern "C" void kernel_launch(void* const* d_in, const int* in_sizes, int n_in,
                              void* d_out, int out_size)
{
    const float* x       = (const float*)d_in[0];
    const float* W_qkv   = (const float*)d_in[1];
    const float* W_out   = (const float*)d_in[2];
    const float* b_out   = (const float*)d_in[3];
    const float* W_cross = (const float*)d_in[4];
    const float* b_cross = (const float*)d_in[5];
    const int*   jitter  = (const int*)d_in[6];
    float* out = (float*)d_out;

    cudaFuncSetAttribute(hgemm<0>, cudaFuncAttributeMaxDynamicSharedMemorySize, SMEM_GEMM);
    cudaFuncSetAttribute(hgemm<1>, cudaFuncAttributeMaxDynamicSharedMemorySize, SMEM_GEMM);
    cudaFuncSetAttribute(hgemm<2>, cudaFuncAttributeMaxDynamicSharedMemorySize, SMEM_GEMM);

    __half *xh, *wqkvh, *wcrossh, *wouth, *qkvh, *a2h;
    cudaGetSymbolAddress((void**)&xh, g_xh);
    cudaGetSymbolAddress((void**)&wqkvh, g_wqkvh);
    cudaGetSymbolAddress((void**)&wcrossh, g_wcrossh);
    cudaGetSymbolAddress((void**)&wouth, g_wouth);
    cudaGetSymbolAddress((void**)&qkvh, g_qkvh);
    cudaGetSymbolAddress((void**)&a2h, g_a2h);

    cvt_half_k<<<(Mv * Dv / 4 + 255) / 256, 256>>>(x, xh, Mv * Dv / 4);
    cvt_half_k<<<(K3v * Dv / 4 + 255) / 256, 256>>>(W_qkv, wqkvh, K3v * Dv / 4);
    cvt_half_k<<<(Dv * Dv / 4 + 255) / 256, 256>>>(W_cross, wcrossh, Dv * Dv / 4);
    cvt_half_k<<<(Dv * Dv / 4 + 255) / 256, 256>>>(W_out, wouth, Dv * Dv / 4);
    zero_scores_k<<<16, 1024>>>();

    hgemm<0><<<dim3(24, 128), 256, SMEM_GEMM>>>(xh, wqkvh, nullptr, qkvh, nullptr, K3v);
    hgemm<1><<<dim3(8, 128), 256, SMEM_GEMM>>>(xh, wcrossh, nullptr, nullptr, b_cross, Dv);
    attn_k<<<Bv * 16 * NWv, 128>>>();
    summary_k<<<Bv * NWv, 256>>>(x);
    cs_k<<<Bv * NWv, 256>>>(jitter);
    fuse_k<<<Mv * Dv / 4 / 256, 256>>>();
    hgemm<2><<<dim3(8, 128), 256, SMEM_GEMM>>>(a2h, wouth, out, nullptr, b_out, Dv);
}

// round 6
// speedup vs baseline: 6.8105x; 1.1737x over previous
#include <cuda_runtime.h>
#include <cuda_fp16.h>
#include <math.h>
#include <stdint.h>

// Problem constants
#define Bv   4
#define Tv   4096
#define Dv   1024
#define NWv  64
#define Mv   16384          // B*T token rows
#define K3v  3072

// ---------------- scratch (device globals; no runtime allocation) ----------
__device__ __half g_xh[(size_t)Mv * Dv];
__device__ __half g_wqkvh[(size_t)K3v * Dv];
__device__ __half g_wcrossh[(size_t)Dv * Dv];
__device__ __half g_wouth[(size_t)Dv * Dv];
__device__ __half g_qkvh[(size_t)Mv * K3v];
__device__ __half g_localh[(size_t)Mv * Dv];
__device__ __half g_a2h[(size_t)Mv * Dv];
__device__ float  g_scores[Mv];
__device__ float  g_sum[Bv * NWv * Dv];
__device__ float  g_cs[Bv * NWv * Dv];

// ---------------------------------------------------------------------------
__device__ __forceinline__ uint32_t smem_u32(const void* p) {
    uint32_t a;
    asm("{ .reg .u64 t; cvta.to.shared.u64 t, %1; cvt.u32.u64 %0, t; }"
        : "=r"(a) : "l"(p));
    return a;
}
#define CP16(dst, src) \
    asm volatile("cp.async.cg.shared.global [%0], [%1], 16;" :: "r"(dst), "l"(src))
#define CPCOMMIT() asm volatile("cp.async.commit_group;" ::: "memory")
#define CPWAIT0()  asm volatile("cp.async.wait_group 0;" ::: "memory")
#define CPWAIT1()  asm volatile("cp.async.wait_group 1;" ::: "memory")

#define LDSM4(r0, r1, r2, r3, addr) \
    asm volatile("ldmatrix.sync.aligned.m8n8.x4.shared.b16 {%0,%1,%2,%3}, [%4];" \
        : "=r"(r0), "=r"(r1), "=r"(r2), "=r"(r3) : "r"(addr))

__device__ __forceinline__ void mma16816(float* d, const uint32_t* a, const uint32_t* b) {
    asm volatile(
        "mma.sync.aligned.m16n8k16.row.col.f32.f16.f16.f32 "
        "{%0,%1,%2,%3}, {%4,%5,%6,%7}, {%8,%9}, {%0,%1,%2,%3};"
        : "+f"(d[0]), "+f"(d[1]), "+f"(d[2]), "+f"(d[3])
        : "r"(a[0]), "r"(a[1]), "r"(a[2]), "r"(a[3]), "r"(b[0]), "r"(b[1]));
}
__device__ __forceinline__ uint32_t packh2(float x, float y) {
    uint32_t r;
    asm("cvt.rn.f16x2.f32 %0, %1, %2;" : "=r"(r) : "f"(y), "f"(x));
    return r;
}

// ---------------------------------------------------------------------------
__global__ void cvt_half_k(const float* __restrict__ s, __half* __restrict__ d, int n4)
{
    const int i = blockIdx.x * blockDim.x + threadIdx.x;
    if (i < n4) {
        const float4 v = ((const float4*)s)[i];
        ((__half2*)d)[i * 2]     = __floats2half2_rn(v.x, v.y);
        ((__half2*)d)[i * 2 + 1] = __floats2half2_rn(v.z, v.w);
    }
}

// ---------------------------------------------------------------------------
// fp16 tensor-core GEMM, CTA 128x128, BK=64, 2-stage cp.async, 2 CTAs/SM.
// Fragments via ldmatrix.x4.  MODE 0: -> Ch (half). MODE 1: atomicAdd rowsum
// tanh(c+bias). MODE 2: -> Cf + bias.
// ---------------------------------------------------------------------------
#define TILEB 18432                     // 128 * 144
#define BUFB  (2 * TILEB)               // A + B per stage
#define SMEM_GEMM (2 * BUFB)            // 73728

template <int MODE>
__global__ void __launch_bounds__(256, 2)
hgemm(const __half* __restrict__ Ah, const __half* __restrict__ Bh,
      float* __restrict__ Cf, __half* __restrict__ Ch,
      const float* __restrict__ bias, int N)
{
    extern __shared__ __align__(16) char sm[];
    const int tid = threadIdx.x;
    const int w = tid >> 5, l = tid & 31;
    const int row0 = blockIdx.y * 128;
    const int col0 = blockIdx.x * 128;
    const int wm = (w >> 2) * 64;
    const int wn = (w & 3) * 32;

    float acc[4][4][4];
#pragma unroll
    for (int a = 0; a < 4; a++)
#pragma unroll
        for (int b = 0; b < 4; b++)
#pragma unroll
            for (int c = 0; c < 4; c++) acc[a][b][c] = 0.f;

    const uint32_t sb = smem_u32(sm);

    auto issue = [&](int t, int buf) {
        const __half* Asrc = Ah + (size_t)row0 * Dv + t * 64;
        const __half* Bsrc = Bh + (size_t)col0 * Dv + t * 64;
        const uint32_t dA = sb + buf * BUFB;
        const uint32_t dB = dA + TILEB;
#pragma unroll
        for (int it = 0; it < 4; it++) {
            const int idx = it * 256 + tid;
            const int m = idx >> 3, kq = idx & 7;
            CP16(dA + m * 144 + kq * 16, Asrc + (size_t)m * Dv + kq * 8);
            CP16(dB + m * 144 + kq * 16, Bsrc + (size_t)m * Dv + kq * 8);
        }
        CPCOMMIT();
    };

    issue(0, 0);
    issue(1, 1);

    // ldmatrix lane offsets (bytes within a stage buffer)
    uint32_t offA[4], offB[2];
#pragma unroll
    for (int mt = 0; mt < 4; mt++)
        offA[mt] = (uint32_t)(wm + mt * 16 + (l & 15)) * 144 + (l >> 4) * 16;
#pragma unroll
    for (int p = 0; p < 2; p++)
        offB[p] = (uint32_t)(TILEB + (wn + p * 16 + ((l >> 4) << 3) + (l & 7)) * 144
                             + ((l >> 3) & 1) * 16);

    for (int t = 0; t < 16; t++) {
        if (t < 15) CPWAIT1(); else CPWAIT0();
        __syncthreads();

        const uint32_t bb = sb + (t & 1) * BUFB;
#pragma unroll
        for (int kt = 0; kt < 4; kt++) {
            const uint32_t ko = kt * 32;
            uint32_t a[4][4], b[4][2];
#pragma unroll
            for (int mt = 0; mt < 4; mt++)
                LDSM4(a[mt][0], a[mt][1], a[mt][2], a[mt][3], bb + offA[mt] + ko);
#pragma unroll
            for (int p = 0; p < 2; p++)
                LDSM4(b[2 * p][0], b[2 * p][1], b[2 * p + 1][0], b[2 * p + 1][1],
                      bb + offB[p] + ko);
#pragma unroll
            for (int mt = 0; mt < 4; mt++)
#pragma unroll
                for (int nt = 0; nt < 4; nt++)
                    mma16816(acc[mt][nt], a[mt], b[nt]);
        }
        __syncthreads();
        if (t + 2 < 16) issue(t + 2, t & 1);
    }

    const int rbase = row0 + wm + (l >> 2);
    const int cbase = col0 + wn + (l & 3) * 2;

    if (MODE == 1) {
#pragma unroll
        for (int mt = 0; mt < 4; mt++) {
            float s0 = 0.f, s1 = 0.f;
#pragma unroll
            for (int nt = 0; nt < 4; nt++) {
                const int c = cbase + nt * 8;
                const float b0 = bias[c], b1 = bias[c + 1];
                s0 += tanhf(acc[mt][nt][0] + b0) + tanhf(acc[mt][nt][1] + b1);
                s1 += tanhf(acc[mt][nt][2] + b0) + tanhf(acc[mt][nt][3] + b1);
            }
            s0 += __shfl_xor_sync(0xffffffffu, s0, 1);
            s0 += __shfl_xor_sync(0xffffffffu, s0, 2);
            s1 += __shfl_xor_sync(0xffffffffu, s1, 1);
            s1 += __shfl_xor_sync(0xffffffffu, s1, 2);
            if ((l & 3) == 0) {
                atomicAdd(&g_scores[rbase + mt * 16], s0);
                atomicAdd(&g_scores[rbase + mt * 16 + 8], s1);
            }
        }
    } else if (MODE == 0) {
#pragma unroll
        for (int mt = 0; mt < 4; mt++) {
            const int row = rbase + mt * 16;
#pragma unroll
            for (int nt = 0; nt < 4; nt++) {
                const int col = cbase + nt * 8;
                *(__half2*)(Ch + (size_t)row * N + col) =
                    __floats2half2_rn(acc[mt][nt][0], acc[mt][nt][1]);
                *(__half2*)(Ch + (size_t)(row + 8) * N + col) =
                    __floats2half2_rn(acc[mt][nt][2], acc[mt][nt][3]);
            }
        }
    } else {
#pragma unroll
        for (int mt = 0; mt < 4; mt++) {
            const int row = rbase + mt * 16;
#pragma unroll
            for (int nt = 0; nt < 4; nt++) {
                const int col = cbase + nt * 8;
                const float b0 = bias[col], b1 = bias[col + 1];
                *(float2*)(Cf + (size_t)row * N + col) =
                    make_float2(acc[mt][nt][0] + b0, acc[mt][nt][1] + b1);
                *(float2*)(Cf + (size_t)(row + 8) * N + col) =
                    make_float2(acc[mt][nt][2] + b0, acc[mt][nt][3] + b1);
            }
        }
    }
}

// ---------------------------------------------------------------------------
// Tensor-core windowed attention: one CTA (128 thr, 4 warps) per (b, h, n).
// ---------------------------------------------------------------------------
__global__ void __launch_bounds__(128)
attn_k()
{
    __shared__ __align__(16) __half sQ[64 * 72];
    __shared__ __align__(16) __half sK[64 * 72];
    __shared__ __align__(16) __half sVt[64 * 72];   // V transposed: [hd][token]

    const int blk = blockIdx.x;
    const int n = blk & 63;
    const int h = (blk >> 6) & 15;
    const int b = blk >> 10;
    const int tid = threadIdx.x;
    const int w = tid >> 5, l = tid & 31;

    const __half* base = g_qkvh + ((size_t)(b * Tv + n * 64)) * K3v + h * 64;

#pragma unroll
    for (int j = 0; j < 16; j++) {
        const int idx = j * 128 + tid;
        const int r = idx >> 5, c2 = idx & 31;
        const __half* rp = base + (size_t)r * K3v;
        const __half2 qv = *(const __half2*)(rp + c2 * 2);
        const __half2 kv = *(const __half2*)(rp + Dv + c2 * 2);
        const __half2 vv = *(const __half2*)(rp + 2 * Dv + c2 * 2);
        *(__half2*)&sQ[r * 72 + c2 * 2] = qv;
        *(__half2*)&sK[r * 72 + c2 * 2] = kv;
        sVt[(c2 * 2) * 72 + r]     = __low2half(vv);
        sVt[(c2 * 2 + 1) * 72 + r] = __high2half(vv);
    }
    __syncthreads();

    const int gr = l >> 2;
    const int gc = (l & 3) * 2;

    float sacc[8][4];
#pragma unroll
    for (int nt = 0; nt < 8; nt++)
#pragma unroll
        for (int c = 0; c < 4; c++) sacc[nt][c] = 0.f;

#pragma unroll
    for (int kt = 0; kt < 4; kt++) {
        uint32_t a[4];
        const __half* qp = sQ + (w * 16 + gr) * 72 + kt * 16 + gc;
        a[0] = *(const uint32_t*)(qp);
        a[1] = *(const uint32_t*)(qp + 8 * 72);
        a[2] = *(const uint32_t*)(qp + 8);
        a[3] = *(const uint32_t*)(qp + 8 * 72 + 8);
#pragma unroll
        for (int nt = 0; nt < 8; nt++) {
            uint32_t bb[2];
            const __half* kp = sK + (nt * 8 + gr) * 72 + kt * 16 + gc;
            bb[0] = *(const uint32_t*)(kp);
            bb[1] = *(const uint32_t*)(kp + 8);
            mma16816(sacc[nt], a, bb);
        }
    }

    float m0 = -1e30f, m1 = -1e30f;
#pragma unroll
    for (int nt = 0; nt < 8; nt++) {
#pragma unroll
        for (int c = 0; c < 4; c++) sacc[nt][c] *= 0.125f;
        m0 = fmaxf(m0, fmaxf(sacc[nt][0], sacc[nt][1]));
        m1 = fmaxf(m1, fmaxf(sacc[nt][2], sacc[nt][3]));
    }
    m0 = fmaxf(m0, __shfl_xor_sync(0xffffffffu, m0, 1));
    m0 = fmaxf(m0, __shfl_xor_sync(0xffffffffu, m0, 2));
    m1 = fmaxf(m1, __shfl_xor_sync(0xffffffffu, m1, 1));
    m1 = fmaxf(m1, __shfl_xor_sync(0xffffffffu, m1, 2));

    float s0 = 0.f, s1 = 0.f;
#pragma unroll
    for (int nt = 0; nt < 8; nt++) {
        sacc[nt][0] = __expf(sacc[nt][0] - m0);
        sacc[nt][1] = __expf(sacc[nt][1] - m0);
        sacc[nt][2] = __expf(sacc[nt][2] - m1);
        sacc[nt][3] = __expf(sacc[nt][3] - m1);
        s0 += sacc[nt][0] + sacc[nt][1];
        s1 += sacc[nt][2] + sacc[nt][3];
    }
    s0 += __shfl_xor_sync(0xffffffffu, s0, 1);
    s0 += __shfl_xor_sync(0xffffffffu, s0, 2);
    s1 += __shfl_xor_sync(0xffffffffu, s1, 1);
    s1 += __shfl_xor_sync(0xffffffffu, s1, 2);
    const float i0 = 1.f / s0, i1 = 1.f / s1;
#pragma unroll
    for (int nt = 0; nt < 8; nt++) {
        sacc[nt][0] *= i0; sacc[nt][1] *= i0;
        sacc[nt][2] *= i1; sacc[nt][3] *= i1;
    }

    float oacc[8][4];
#pragma unroll
    for (int nt = 0; nt < 8; nt++)
#pragma unroll
        for (int c = 0; c < 4; c++) oacc[nt][c] = 0.f;

#pragma unroll
    for (int kt = 0; kt < 4; kt++) {
        uint32_t a[4];
        a[0] = packh2(sacc[2 * kt][0],     sacc[2 * kt][1]);
        a[1] = packh2(sacc[2 * kt][2],     sacc[2 * kt][3]);
        a[2] = packh2(sacc[2 * kt + 1][0], sacc[2 * kt + 1][1]);
        a[3] = packh2(sacc[2 * kt + 1][2], sacc[2 * kt + 1][3]);
#pragma unroll
        for (int nt = 0; nt < 8; nt++) {
            uint32_t bb[2];
            const __half* vp = sVt + (nt * 8 + gr) * 72 + kt * 16 + gc;
            bb[0] = *(const uint32_t*)(vp);
            bb[1] = *(const uint32_t*)(vp + 8);
            mma16816(oacc[nt], a, bb);
        }
    }

    __half* op = g_localh + ((size_t)(b * Tv + n * 64)) * Dv + h * 64;
    const int orow = w * 16 + gr;
#pragma unroll
    for (int nt = 0; nt < 8; nt++) {
        const int col = nt * 8 + gc;
        *(__half2*)(op + (size_t)orow * Dv + col) =
            __floats2half2_rn(oacc[nt][0], oacc[nt][1]);
        *(__half2*)(op + (size_t)(orow + 8) * Dv + col) =
            __floats2half2_rn(oacc[nt][2], oacc[nt][3]);
    }
}

// ---------------------------------------------------------------------------
__global__ void zero_scores_k()
{
    const int i = blockIdx.x * blockDim.x + threadIdx.x;
    if (i < Mv) g_scores[i] = 0.f;
}

__global__ void __launch_bounds__(256)
summary_k(const float* __restrict__ x)
{
    __shared__ float wsh[64];
    const int blk = blockIdx.x;
    const int base = blk * 64;
    const int tid = threadIdx.x;

    if (tid < 64) wsh[tid] = g_scores[base + tid] * (1.0f / 1024.0f);
    __syncthreads();

    float mx = -1e30f;
    for (int w = 0; w < 64; w++) mx = fmaxf(mx, wsh[w]);
    float sum = 0.f;
    for (int w = 0; w < 64; w++) sum += __expf(wsh[w] - mx);
    __syncthreads();
    if (tid < 64) wsh[tid] = __expf(wsh[tid] - mx) / sum;
    __syncthreads();

    for (int d = tid; d < Dv; d += 256) {
        float acc = 0.f;
        const float* xp = x + (size_t)base * Dv + d;
#pragma unroll 8
        for (int w = 0; w < 64; w++) acc += wsh[w] * xp[(size_t)w * Dv];
        g_sum[(size_t)blk * Dv + d] = acc;
    }
}

__global__ void __launch_bounds__(256)
cs_k(const int* __restrict__ jitter)
{
    __shared__ float lg[64];
    __shared__ float p[64];
    __shared__ int jit[64];
    const int blk = blockIdx.x;
    const int b = blk >> 6;
    const int tid = threadIdx.x;

    if (tid < 64) jit[tid] = jitter[tid];
    __syncthreads();

    const float* srow = g_sum + (size_t)blk * Dv;
    const int wid = tid >> 5, lane = tid & 31;
    for (int m8 = 0; m8 < 8; m8++) {
        const int m = wid * 8 + m8;
        const float* jrow = g_sum + (size_t)(b * 64 + jit[m]) * Dv;
        float a = 0.f;
        for (int d = lane; d < Dv; d += 32) a += srow[d] * jrow[d];
#pragma unroll
        for (int off = 16; off; off >>= 1) a += __shfl_xor_sync(0xffffffffu, a, off);
        if (lane == 0) lg[m] = a * (1.0f / 32.0f);
    }
    __syncthreads();

    float mx = -1e30f;
    for (int m = 0; m < 64; m++) mx = fmaxf(mx, lg[m]);
    float sum = 0.f;
    for (int m = 0; m < 64; m++) sum += __expf(lg[m] - mx);
    __syncthreads();
    if (tid < 64) p[tid] = __expf(lg[tid] - mx) / sum;
    __syncthreads();

    for (int d = tid; d < Dv; d += 256) {
        float acc = 0.f;
#pragma unroll 8
        for (int m = 0; m < 64; m++)
            acc += p[m] * g_sum[(size_t)(b * 64 + jit[m]) * Dv + d];
        g_cs[(size_t)blk * Dv + d] = acc;
    }
}

__global__ void fuse_k()
{
    const size_t i = (size_t)blockIdx.x * blockDim.x + threadIdx.x;
    const size_t e = i * 4;
    if (e < (size_t)Mv * Dv) {
        const int m = (int)(e >> 10), d = (int)(e & 1023);
        const __half2 l0 = *(const __half2*)(g_localh + e);
        const __half2 l1 = *(const __half2*)(g_localh + e + 2);
        const float4 c = *(const float4*)(g_cs + (size_t)(m >> 6) * Dv + d);
        const float2 f0 = __half22float2(l0), f1 = __half22float2(l1);
        *(__half2*)(g_a2h + e) =
            __floats2half2_rn(f0.x + 0.25f * c.x, f0.y + 0.25f * c.y);
        *(__half2*)(g_a2h + e + 2) =
            __floats2half2_rn(f1.x + 0.25f * c.z, f1.y + 0.25f * c.w);
    }
}

// ---------------------------------------------------------------------------
extern "C" void kernel_launch(void* const* d_in, const int* in_sizes, int n_in,
                              void* d_out, int out_size)
{
    const float* x       = (const float*)d_in[0];
    const float* W_qkv   = (const float*)d_in[1];
    const float* W_out   = (const float*)d_in[2];
    const float* b_out   = (const float*)d_in[3];
    const float* W_cross = (const float*)d_in[4];
    const float* b_cross = (const float*)d_in[5];
    const int*   jitter  = (const int*)d_in[6];
    float* out = (float*)d_out;

    cudaFuncSetAttribute(hgemm<0>, cudaFuncAttributeMaxDynamicSharedMemorySize, SMEM_GEMM);
    cudaFuncSetAttribute(hgemm<1>, cudaFuncAttributeMaxDynamicSharedMemorySize, SMEM_GEMM);
    cudaFuncSetAttribute(hgemm<2>, cudaFuncAttributeMaxDynamicSharedMemorySize, SMEM_GEMM);

    __half *xh, *wqkvh, *wcrossh, *wouth, *qkvh, *a2h;
    cudaGetSymbolAddress((void**)&xh, g_xh);
    cudaGetSymbolAddress((void**)&wqkvh, g_wqkvh);
    cudaGetSymbolAddress((void**)&wcrossh, g_wcrossh);
    cudaGetSymbolAddress((void**)&wouth, g_wouth);
    cudaGetSymbolAddress((void**)&qkvh, g_qkvh);
    cudaGetSymbolAddress((void**)&a2h, g_a2h);

    cvt_half_k<<<(Mv * Dv / 4 + 255) / 256, 256>>>(x, xh, Mv * Dv / 4);
    cvt_half_k<<<(K3v * Dv / 4 + 255) / 256, 256>>>(W_qkv, wqkvh, K3v * Dv / 4);
    cvt_half_k<<<(Dv * Dv / 4 + 255) / 256, 256>>>(W_cross, wcrossh, Dv * Dv / 4);
    cvt_half_k<<<(Dv * Dv / 4 + 255) / 256, 256>>>(W_out, wouth, Dv * Dv / 4);
    zero_scores_k<<<16, 1024>>>();

    hgemm<0><<<dim3(24, 128), 256, SMEM_GEMM>>>(xh, wqkvh, nullptr, qkvh, nullptr, K3v);
    hgemm<1><<<dim3(8, 128), 256, SMEM_GEMM>>>(xh, wcrossh, nullptr, nullptr, b_cross, Dv);
    attn_k<<<Bv * 16 * NWv, 128>>>();
    summary_k<<<Bv * NWv, 256>>>(x);
    cs_k<<<Bv * NWv, 256>>>(jitter);
    fuse_k<<<Mv * Dv / 4 / 256, 256>>>();
    hgemm<2><<<dim3(8, 128), 256, SMEM_GEMM>>>(a2h, wouth, out, nullptr, b_out, Dv);
}